// round 15
// baseline (speedup 1.0000x reference)
#include <cuda_runtime.h>
#include <math.h>

#define NB 32
#define NT 512
#define NE 300
#define NH 512
#define NG 2048   // 4*NH

#define NCTA_B 128
#define THR_B  512

#define HS_STRIDE 36          // floats per h row (32 used)
#define US_STRIDE 18          // u64 per U row (16 used)
#define RED_ROW   520         // floats per kt row (512 used)

#define GATE_STRIDE (NH * NB)   // 16384 floats between gates in g_xz

// kernel A: 64x64 tile, BK=20 (300 = 15*20; 80B chunks -> 16B-aligned float4)
#define BKA 20

typedef unsigned long long u64;

// ---------------------------------------------------------------------------
__device__ __forceinline__ u64 pack2(float lo, float hi) {
    u64 r; asm("mov.b64 %0, {%1,%2};" : "=l"(r) : "f"(lo), "f"(hi)); return r;
}
__device__ __forceinline__ void fma2(u64& d, u64 a, u64 b) {
    asm("fma.rn.f32x2 %0, %1, %2, %0;" : "+l"(d) : "l"(a), "l"(b));
}
__device__ __forceinline__ float2 unpack2(u64 v) {
    float2 f; asm("mov.b64 {%0,%1}, %2;" : "=f"(f.x), "=f"(f.y) : "l"(v)); return f;
}

__device__ __forceinline__ float fast_sig(float x) {
    float e = __expf(-x);
    return __fdividef(1.f, 1.f + e);
}
__device__ __forceinline__ float fast_tanh(float x) {
    float e = __expf(2.f * x);              // inf-safe
    return 1.f - 2.f * __fdividef(1.f, e + 1.f);
}

__device__ __forceinline__ void bar_release_add(unsigned int* p) {
    asm volatile("red.release.gpu.global.add.u32 [%0], %1;"
                 :: "l"(p), "r"(1u) : "memory");
}
__device__ __forceinline__ unsigned int bar_acquire_ld(unsigned int* p) {
    unsigned int v;
    asm volatile("ld.acquire.gpu.global.u32 %0, [%1];"
                 : "=r"(v) : "l"(p) : "memory");
    return v;
}

// Scratch (device globals)
// xz layout: [t][gate][j][b]  (b contiguous -> coalesced writes AND reads)
__device__ float g_xz[(size_t)NT * 4 * NH * NB];
__device__ float g_h[2][NH * NB];              // ping-pong h, [k][b]
__device__ unsigned int g_bar;

// ---------------------------------------------------------------------------
// Kernel A: z[t][n][b] = sum_k emb[tok(b,t)][k] * W[k][n] + bias[n]
// 64x64 tile, BK=20, float4 gathers for emb AND W; staged coalesced epilogue
// into [t][gate][j][b]. Also zeroes g_h / g_bar.
// ---------------------------------------------------------------------------
__global__ __launch_bounds__(256) void xz_kernel(
    const int* __restrict__ tokens, const float* __restrict__ emb,
    const float* __restrict__ W, const float* __restrict__ bias)
{
    __shared__ float As[BKA * 68];       // [kk][m]
    __shared__ u64   Bs2[BKA * 68];      // [kk][n] dup pairs
    __shared__ int   toks[64];
    __shared__ float stage[64 * 68];     // [n][m], stride 68

    int tid = threadIdx.x;
    int m0 = blockIdx.y * 64;
    int n0 = blockIdx.x * 64;

    if (blockIdx.x == 0 && blockIdx.y < 32) {
        int i = blockIdx.y * 256 + tid;
        ((float4*)g_h)[i] = make_float4(0.f, 0.f, 0.f, 0.f);
        if (i == 0) g_bar = 0u;
    }

    if (tid < 64) {
        int m = m0 + tid;
        toks[tid] = tokens[(m & 31) * NT + (m >> 5)];
    }
    __syncthreads();

    int tm = tid & 15, tn = tid >> 4;
    u64 acc2[2][4];
    #pragma unroll
    for (int p = 0; p < 2; ++p)
        #pragma unroll
        for (int j = 0; j < 4; ++j) acc2[p][j] = 0ull;

    for (int k0 = 0; k0 < NE; k0 += BKA) {
        // As: float4 gathers (row base tok*1200B and 80B chunks -> 16B-aligned)
        for (int idx = tid; idx < 64 * 5; idx += 256) {        // 320 float4
            int row = idx / 5, seg = idx - row * 5;
            float4 e = *(const float4*)&emb[(size_t)toks[row] * NE + k0 + seg * 4];
            int kk = seg * 4;
            As[(kk + 0) * 68 + row] = e.x;
            As[(kk + 1) * 68 + row] = e.y;
            As[(kk + 2) * 68 + row] = e.z;
            As[(kk + 3) * 68 + row] = e.w;
        }
        // Bs: float4 loads of W rows -> dup pairs
        for (int idx = tid; idx < BKA * 16; idx += 256) {      // 320 float4
            int kk = idx >> 4, nq = idx & 15;
            float4 w = *(const float4*)&W[(size_t)(k0 + kk) * NG + n0 + nq * 4];
            u64* dst = Bs2 + kk * 68 + nq * 4;
            dst[0] = pack2(w.x, w.x);
            dst[1] = pack2(w.y, w.y);
            dst[2] = pack2(w.z, w.z);
            dst[3] = pack2(w.w, w.w);
        }
        __syncthreads();

        #pragma unroll
        for (int kk = 0; kk < BKA; ++kk) {
            float4 av = *(const float4*)&As[kk * 68 + tm * 4];
            ulonglong2 b01 = *(const ulonglong2*)&Bs2[kk * 68 + tn * 4];
            ulonglong2 b23 = *(const ulonglong2*)&Bs2[kk * 68 + tn * 4 + 2];
            u64 ap[2] = { pack2(av.x, av.y), pack2(av.z, av.w) };
            u64 bd[4] = { b01.x, b01.y, b23.x, b23.y };
            #pragma unroll
            for (int p = 0; p < 2; ++p)
                #pragma unroll
                for (int j = 0; j < 4; ++j)
                    fma2(acc2[p][j], ap[p], bd[j]);
        }
        __syncthreads();
    }

    // ---- epilogue: stage (bias folded) -> coalesced STG.128 ----
    #pragma unroll
    for (int j = 0; j < 4; ++j) {
        int n = tn * 4 + j;
        float bb = bias[n0 + n];
        #pragma unroll
        for (int p = 0; p < 2; ++p) {
            float2 v = unpack2(acc2[p][j]);
            int m = tm * 4 + p * 2;
            stage[n * 68 + m]     = v.x + bb;
            stage[n * 68 + m + 1] = v.y + bb;
        }
    }
    __syncthreads();

    {
        int t0 = m0 >> 5;                    // first t of this tile
        int gate = n0 >> 9, col0 = n0 & 511;
        int s = tid >> 1, half = tid & 1;    // s: 0..127 = (tl, col)
        int tl = s >> 6, col = s & 63;
        const float4* src = (const float4*)(stage + col * 68 + tl * 32 + half * 16);
        float4* dst = (float4*)&g_xz[(((size_t)(t0 + tl) * 4 + gate) * NH
                                      + (col0 + col)) * NB + half * 16];
        #pragma unroll
        for (int q = 0; q < 4; ++q)
            __stcs(dst + q, src[q]);
    }
}

// ---------------------------------------------------------------------------
// Kernel B: persistent LSTM (R5 structure — frozen). 128 CTAs x 512 thr.
// Warp 12 stages the FULL 2KB xz block (128 float4, 4 per lane) into smem,
// hidden under copy+GEMM; gate threads read conflict-free LDS.
// ---------------------------------------------------------------------------
__global__ __launch_bounds__(THR_B) void lstm_kernel(
    const float* __restrict__ U, float* __restrict__ out)
{
    extern __shared__ float sm[];
    u64*   us2 = (u64*)sm;                      // [512][US_STRIDE] u64
    float* hs  = (float*)(us2 + NH * US_STRIDE);// [512][HS_STRIDE]
    float* red = hs + NH * HS_STRIDE;           // [16][RED_ROW]
    float* zs  = red + 16 * RED_ROW;            // [512]
    float* cs  = zs + 512;                      // [128]
    float* xzs = cs + 128;                      // [4][4][32] = 512

    int tid = threadIdx.x;
    int cta = blockIdx.x;
    int j0 = cta * 4;

    // Load U slice as duplicated pairs: col c = gate*4+jj -> U[k][gate*512+j0+jj]
    for (int idx = tid; idx < NH * 16; idx += THR_B) {
        int k = idx >> 4, c = idx & 15;
        int col = (c >> 2) * NH + j0 + (c & 3);
        float u = U[(size_t)k * NG + col];
        us2[k * US_STRIDE + c] = pack2(u, u);
    }
    if (tid < 128) cs[tid] = 0.f;
    __syncthreads();

    // warp = kt (16 K-slices); thread tile 4 batches x 4 cols
    int kt = tid >> 5;                          // warp id
    int ot = tid & 31;
    int b0 = (ot & 7) * 4;                      // 8 b-tiles of 4
    int c0 = (ot >> 3) * 4;                     // 4 c-tiles of 4
    int jj = tid >> 5, bb = tid & 31;           // gates mapping (tid<128)

    for (int t = 0; t < NT; ++t) {
        int parity = t & 1;

        // warp 12: stage the FULL xz block (4 gates x 32 float4) into smem.
        // Ordered vs gate reads by the zs __syncthreads; vs previous step's
        // reads by the end-of-step barrier's two __syncthreads.
        if (kt == 12) {
            const float4* gx4 = (const float4*)g_xz;
            #pragma unroll
            for (int r = 0; r < 4; ++r) {
                int idx = r * 32 + ot;          // 0..127 float4
                int gsel = idx >> 5, q = idx & 31;
                size_t base4 = ((size_t)(t * 4 + gsel) * NH + j0) * NB / 4;
                float4 v = __ldcs(gx4 + base4 + q);
                *(float4*)(xzs + gsel * 128 + q * 4) = v;
            }
        }

        const float4* gh4 = (const float4*)g_h[parity];

        // ---- chunk 0 copy (rows 0..127 = 1024 float4, 2 per thread) ----
        #pragma unroll
        for (int r = 0; r < 2; ++r) {
            int f = r * 512 + tid;
            float4 v = __ldcg(gh4 + f);
            int base = f * 4;
            *(float4*)(hs + (base >> 5) * HS_STRIDE + (base & 31)) = v;
        }
        __syncthreads();

        u64 acc2[2][4];
        #pragma unroll
        for (int i = 0; i < 2; ++i)
            #pragma unroll
            for (int j = 0; j < 4; ++j) acc2[i][j] = 0ull;

        // ---- pipelined chunks: prefetch next, GEMM current ----
        #pragma unroll
        for (int c = 0; c < 4; ++c) {
            float4 pre[2];
            if (c < 3) {
                #pragma unroll
                for (int r = 0; r < 2; ++r)
                    pre[r] = __ldcg(gh4 + (c + 1) * 1024 + r * 512 + tid);
            }

            #pragma unroll
            for (int i = 0; i < 8; ++i) {
                int kk = 128 * c + 16 * i + kt;
                float4 hv = *(const float4*)(hs + kk * HS_STRIDE + b0);
                const u64* urow = us2 + kk * US_STRIDE + c0;
                ulonglong2 ua = *(const ulonglong2*)urow;
                ulonglong2 ub = *(const ulonglong2*)(urow + 2);
                u64 hp[2] = { pack2(hv.x, hv.y), pack2(hv.z, hv.w) };
                u64 up[4] = { ua.x, ua.y, ub.x, ub.y };
                #pragma unroll
                for (int p = 0; p < 2; ++p)
                    #pragma unroll
                    for (int j = 0; j < 4; ++j)
                        fma2(acc2[p][j], hp[p], up[j]);
            }

            if (c < 3) {
                #pragma unroll
                for (int r = 0; r < 2; ++r) {
                    int f = (c + 1) * 1024 + r * 512 + tid;
                    int base = f * 4;
                    *(float4*)(hs + (base >> 5) * HS_STRIDE + (base & 31)) = pre[r];
                }
                __syncthreads();
            }
        }

        // K-split partials: red[kt][c*32 + b]
        #pragma unroll
        for (int j = 0; j < 4; ++j) {
            float2 v0 = unpack2(acc2[0][j]);
            float2 v1 = unpack2(acc2[1][j]);
            *(float4*)(red + kt * RED_ROW + (c0 + j) * 32 + b0) =
                make_float4(v0.x, v0.y, v1.x, v1.y);
        }
        __syncthreads();

        // 512 outputs / 512 threads: 1 each
        {
            int o = tid;
            float s = 0.f;
            #pragma unroll
            for (int q = 0; q < 16; ++q) s += red[q * RED_ROW + o];
            zs[o] = s;
        }
        __syncthreads();

        // Gates + state update (thread = (jj, bb), 128 threads)
        if (tid < 128) {
            int xo = jj * 32 + bb;
            float zi = zs[(0 * 4 + jj) * 32 + bb] + xzs[0 * 128 + xo];
            float zf = zs[(1 * 4 + jj) * 32 + bb] + xzs[1 * 128 + xo];
            float zg = zs[(2 * 4 + jj) * 32 + bb] + xzs[2 * 128 + xo];
            float zo = zs[(3 * 4 + jj) * 32 + bb] + xzs[3 * 128 + xo];

            float ig = fast_sig(zi);
            float fg = fast_sig(zf);
            float gg = fast_tanh(zg);
            float og = fast_sig(zo);

            float cn = fg * cs[tid] + ig * gg;
            cs[tid] = cn;
            float hn = og * fast_tanh(cn);

            if (t == NT - 1) {
                out[bb * NH + (j0 + jj)] = hn;             // hidden [B,H]
                out[NB * NH + bb * NH + (j0 + jj)] = cn;   // cell   [B,H]
            } else {
                __stcg(&g_h[parity ^ 1][(j0 + jj) * NB + bb], hn);
            }
        }

        // Grid-wide barrier: release-increment, acquire-poll
        if (t < NT - 1) {
            __syncthreads();
            if (tid == 0) {
                bar_release_add(&g_bar);
                unsigned target = (unsigned)NCTA_B * (unsigned)(t + 1);
                while (bar_acquire_ld(&g_bar) < target) { }
            }
            __syncthreads();
        }
    }
}

// ---------------------------------------------------------------------------
extern "C" void kernel_launch(void* const* d_in, const int* in_sizes, int n_in,
                              void* d_out, int out_size) {
    const int*   tokens = (const int*)d_in[0];
    const float* emb    = (const float*)d_in[1];
    const float* W      = (const float*)d_in[2];
    const float* U      = (const float*)d_in[3];
    const float* bias   = (const float*)d_in[4];
    float* out = (float*)d_out;

    dim3 ga(NG / 64, (NB * NT) / 64);   // (32, 256)
    xz_kernel<<<ga, 256>>>(tokens, emb, W, bias);

    int smem = (int)(NH * US_STRIDE * sizeof(u64) +
                     (NH * HS_STRIDE + 16 * RED_ROW + 512 + 128 + 512) * sizeof(float));
    cudaFuncSetAttribute(lstm_kernel, cudaFuncAttributeMaxDynamicSharedMemorySize, smem);
    lstm_kernel<<<NCTA_B, THR_B, smem>>>(U, out);
}

// round 16
// speedup vs baseline: 1.0883x; 1.0883x over previous
#include <cuda_runtime.h>
#include <math.h>

#define NB 32
#define NT 512
#define NE 300
#define NH 512
#define NG 2048   // 4*NH

#define NCTA_B 128
#define THR_B  512

#define HS_STRIDE 36          // floats per h row (32 used)
#define US_STRIDE 18          // u64 per U row (16 used)
#define RED_ROW   520         // floats per kt row (512 used)

// kernel A: 64(M) x 64(N) tile, BK=20; N-tile spans 4 gates x 16 j-cols
#define BKA 20

typedef unsigned long long u64;

// ---------------------------------------------------------------------------
__device__ __forceinline__ u64 pack2(float lo, float hi) {
    u64 r; asm("mov.b64 %0, {%1,%2};" : "=l"(r) : "f"(lo), "f"(hi)); return r;
}
__device__ __forceinline__ void fma2(u64& d, u64 a, u64 b) {
    asm("fma.rn.f32x2 %0, %1, %2, %0;" : "+l"(d) : "l"(a), "l"(b));
}
__device__ __forceinline__ float2 unpack2(u64 v) {
    float2 f; asm("mov.b64 {%0,%1}, %2;" : "=f"(f.x), "=f"(f.y) : "l"(v)); return f;
}

__device__ __forceinline__ float fast_sig(float x) {
    float e = __expf(-x);
    return __fdividef(1.f, 1.f + e);
}
__device__ __forceinline__ float fast_tanh(float x) {
    float e = __expf(2.f * x);              // inf-safe
    return 1.f - 2.f * __fdividef(1.f, e + 1.f);
}

__device__ __forceinline__ void bar_release_add(unsigned int* p) {
    asm volatile("red.release.gpu.global.add.u32 [%0], %1;"
                 :: "l"(p), "r"(1u) : "memory");
}
__device__ __forceinline__ unsigned int bar_acquire_ld(unsigned int* p) {
    unsigned int v;
    asm volatile("ld.acquire.gpu.global.u32 %0, [%1];"
                 : "=r"(v) : "l"(p) : "memory");
    return v;
}

// Scratch (device globals)
// xz layout: [t][j][b][gate]  (one float4 per (t,j,b) -- the R5/2.50ms read)
__device__ float g_xz[(size_t)NT * NH * NB * 4];
__device__ float g_h[2][NH * NB];              // ping-pong h, [k][b]
__device__ unsigned int g_bar;

// ---------------------------------------------------------------------------
// Kernel A: z[t][n][b] = sum_k emb[tok(b,t)][k] * W[k][n] + bias[n]
// N-tile = {gate*512 + j0 + jj}: 4 gates x 16 j -> output block per t is
// 2048 CONTIGUOUS floats in [t][j][b][gate]. BK=20, float4 gathers, staged
// coalesced epilogue. Also zeroes g_h / g_bar.
// ---------------------------------------------------------------------------
__global__ __launch_bounds__(256) void xz_kernel(
    const int* __restrict__ tokens, const float* __restrict__ emb,
    const float* __restrict__ W, const float* __restrict__ bias)
{
    __shared__ float As[BKA * 68];       // [kk][m]
    __shared__ u64   Bs2[BKA * 68];      // [kk][c] dup pairs, c = gate*16+jj
    __shared__ int   toks[64];
    __shared__ float stage[64 * 68];     // [c][m], stride 68

    int tid = threadIdx.x;
    int m0 = blockIdx.y * 64;            // m = t*32 + b
    int j0 = blockIdx.x * 16;            // 16 j-cols, all 4 gates

    if (blockIdx.x == 0 && blockIdx.y < 32) {
        int i = blockIdx.y * 256 + tid;
        ((float4*)g_h)[i] = make_float4(0.f, 0.f, 0.f, 0.f);
        if (i == 0) g_bar = 0u;
    }

    if (tid < 64) {
        int m = m0 + tid;
        toks[tid] = tokens[(m & 31) * NT + (m >> 5)];
    }
    __syncthreads();

    int tm = tid & 15, tn = tid >> 4;
    u64 acc2[2][4];
    #pragma unroll
    for (int p = 0; p < 2; ++p)
        #pragma unroll
        for (int j = 0; j < 4; ++j) acc2[p][j] = 0ull;

    for (int k0 = 0; k0 < NE; k0 += BKA) {
        // As: float4 gathers (row base tok*1200B, 80B chunks -> 16B-aligned)
        for (int idx = tid; idx < 64 * 5; idx += 256) {        // 320 float4
            int row = idx / 5, seg = idx - row * 5;
            float4 e = *(const float4*)&emb[(size_t)toks[row] * NE + k0 + seg * 4];
            int kk = seg * 4;
            As[(kk + 0) * 68 + row] = e.x;
            As[(kk + 1) * 68 + row] = e.y;
            As[(kk + 2) * 68 + row] = e.z;
            As[(kk + 3) * 68 + row] = e.w;
        }
        // Bs: per c4, gate = c4>>2, jj-base = (c4&3)*4; 16B-aligned float4
        for (int idx = tid; idx < BKA * 16; idx += 256) {      // 320 float4
            int kk = idx >> 4, c4 = idx & 15;
            int gate = c4 >> 2, jjb = (c4 & 3) * 4;
            float4 w = *(const float4*)&W[(size_t)(k0 + kk) * NG
                                          + gate * NH + j0 + jjb];
            u64* dst = Bs2 + kk * 68 + gate * 16 + jjb;
            dst[0] = pack2(w.x, w.x);
            dst[1] = pack2(w.y, w.y);
            dst[2] = pack2(w.z, w.z);
            dst[3] = pack2(w.w, w.w);
        }
        __syncthreads();

        #pragma unroll
        for (int kk = 0; kk < BKA; ++kk) {
            float4 av = *(const float4*)&As[kk * 68 + tm * 4];
            ulonglong2 b01 = *(const ulonglong2*)&Bs2[kk * 68 + tn * 4];
            ulonglong2 b23 = *(const ulonglong2*)&Bs2[kk * 68 + tn * 4 + 2];
            u64 ap[2] = { pack2(av.x, av.y), pack2(av.z, av.w) };
            u64 bd[4] = { b01.x, b01.y, b23.x, b23.y };
            #pragma unroll
            for (int p = 0; p < 2; ++p)
                #pragma unroll
                for (int j = 0; j < 4; ++j)
                    fma2(acc2[p][j], ap[p], bd[j]);
        }
        __syncthreads();
    }

    // ---- epilogue: stage (bias folded) ----
    #pragma unroll
    for (int j = 0; j < 4; ++j) {
        int c = tn * 4 + j;                      // gate = c>>4, jj = c&15
        float bb = bias[(c >> 4) * NH + j0 + (c & 15)];
        #pragma unroll
        for (int p = 0; p < 2; ++p) {
            float2 v = unpack2(acc2[p][j]);
            int m = tm * 4 + p * 2;
            stage[c * 68 + m]     = v.x + bb;
            stage[c * 68 + m + 1] = v.y + bb;
        }
    }
    __syncthreads();

    // ---- coalesced write-out: 2048 contiguous floats per t-half ----
    {
        int t0 = m0 >> 5;
        #pragma unroll
        for (int i = 0; i < 4; ++i) {
            int o4 = i * 256 + tid;              // 0..1023 float4
            int tl = o4 >> 9, rem = o4 & 511;
            int jj = rem >> 5, b = rem & 31;
            int ms = tl * 32 + b;
            float4 v;
            v.x = stage[( 0 + jj) * 68 + ms];
            v.y = stage[(16 + jj) * 68 + ms];
            v.z = stage[(32 + jj) * 68 + ms];
            v.w = stage[(48 + jj) * 68 + ms];
            __stcs((float4*)&g_xz[(((size_t)(t0 + tl) * NH + j0 + jj) * NB + b) * 4], v);
        }
    }
}

// ---------------------------------------------------------------------------
// Kernel B: persistent LSTM (R5 verbatim — the 2.50ms engine). 128 CTAs x
// 512 thr; CTA owns 4 h-cols across 4 gates. Warp = one kt slice
// (interleaved K, stride 16). Thread tile 4b x 4c. Chunk-pipelined h copy.
// ---------------------------------------------------------------------------
__global__ __launch_bounds__(THR_B) void lstm_kernel(
    const float* __restrict__ U, float* __restrict__ out)
{
    extern __shared__ float sm[];
    u64*   us2 = (u64*)sm;                      // [512][US_STRIDE] u64
    float* hs  = (float*)(us2 + NH * US_STRIDE);// [512][HS_STRIDE]
    float* red = hs + NH * HS_STRIDE;           // [16][RED_ROW]
    float* zs  = red + 16 * RED_ROW;            // [512]
    float* cs  = zs + 512;                      // [128]

    int tid = threadIdx.x;
    int cta = blockIdx.x;
    int j0 = cta * 4;

    // Load U slice as duplicated pairs: col c = gate*4+jj -> U[k][gate*512+j0+jj]
    for (int idx = tid; idx < NH * 16; idx += THR_B) {
        int k = idx >> 4, c = idx & 15;
        int col = (c >> 2) * NH + j0 + (c & 3);
        float u = U[(size_t)k * NG + col];
        us2[k * US_STRIDE + c] = pack2(u, u);
    }
    if (tid < 128) cs[tid] = 0.f;
    __syncthreads();

    // warp = kt (16 K-slices); thread tile 4 batches x 4 cols
    int kt = tid >> 5;                          // warp id
    int ot = tid & 31;
    int b0 = (ot & 7) * 4;                      // 8 b-tiles of 4
    int c0 = (ot >> 3) * 4;                     // 4 c-tiles of 4
    int jj = tid >> 5, bb = tid & 31;           // gates mapping (tid<128)

    for (int t = 0; t < NT; ++t) {
        int parity = t & 1;

        // Prefetch xz (one coalesced float4 per (j,b) thread)
        float4 xv = make_float4(0.f, 0.f, 0.f, 0.f);
        if (tid < 128)
            xv = __ldcs((const float4*)&g_xz[(((size_t)t * NH + j0 + jj) * NB + bb) * 4]);

        const float4* gh4 = (const float4*)g_h[parity];

        // ---- chunk 0 copy (rows 0..127 = 1024 float4, 2 per thread) ----
        #pragma unroll
        for (int r = 0; r < 2; ++r) {
            int f = r * 512 + tid;
            float4 v = __ldcg(gh4 + f);
            int base = f * 4;
            *(float4*)(hs + (base >> 5) * HS_STRIDE + (base & 31)) = v;
        }
        __syncthreads();

        u64 acc2[2][4];
        #pragma unroll
        for (int i = 0; i < 2; ++i)
            #pragma unroll
            for (int j = 0; j < 4; ++j) acc2[i][j] = 0ull;

        // ---- pipelined chunks: prefetch next, GEMM current ----
        #pragma unroll
        for (int c = 0; c < 4; ++c) {
            float4 pre[2];
            if (c < 3) {
                #pragma unroll
                for (int r = 0; r < 2; ++r)
                    pre[r] = __ldcg(gh4 + (c + 1) * 1024 + r * 512 + tid);
            }

            #pragma unroll
            for (int i = 0; i < 8; ++i) {
                int kk = 128 * c + 16 * i + kt;
                float4 hv = *(const float4*)(hs + kk * HS_STRIDE + b0);
                const u64* urow = us2 + kk * US_STRIDE + c0;
                ulonglong2 ua = *(const ulonglong2*)urow;
                ulonglong2 ub = *(const ulonglong2*)(urow + 2);
                u64 hp[2] = { pack2(hv.x, hv.y), pack2(hv.z, hv.w) };
                u64 up[4] = { ua.x, ua.y, ub.x, ub.y };
                #pragma unroll
                for (int p = 0; p < 2; ++p)
                    #pragma unroll
                    for (int j = 0; j < 4; ++j)
                        fma2(acc2[p][j], hp[p], up[j]);
            }

            if (c < 3) {
                #pragma unroll
                for (int r = 0; r < 2; ++r) {
                    int f = (c + 1) * 1024 + r * 512 + tid;
                    int base = f * 4;
                    *(float4*)(hs + (base >> 5) * HS_STRIDE + (base & 31)) = pre[r];
                }
                __syncthreads();
            }
        }

        // K-split partials: red[kt][c*32 + b]
        #pragma unroll
        for (int j = 0; j < 4; ++j) {
            float2 v0 = unpack2(acc2[0][j]);
            float2 v1 = unpack2(acc2[1][j]);
            *(float4*)(red + kt * RED_ROW + (c0 + j) * 32 + b0) =
                make_float4(v0.x, v0.y, v1.x, v1.y);
        }
        __syncthreads();

        // 512 outputs / 512 threads: 1 each
        {
            int o = tid;
            float s = 0.f;
            #pragma unroll
            for (int q = 0; q < 16; ++q) s += red[q * RED_ROW + o];
            zs[o] = s;
        }
        __syncthreads();

        // Gates + state update (thread = (jj, bb), 128 threads)
        if (tid < 128) {
            float zi = zs[(0 * 4 + jj) * 32 + bb] + xv.x;
            float zf = zs[(1 * 4 + jj) * 32 + bb] + xv.y;
            float zg = zs[(2 * 4 + jj) * 32 + bb] + xv.z;
            float zo = zs[(3 * 4 + jj) * 32 + bb] + xv.w;

            float ig = fast_sig(zi);
            float fg = fast_sig(zf);
            float gg = fast_tanh(zg);
            float og = fast_sig(zo);

            float cn = fg * cs[tid] + ig * gg;
            cs[tid] = cn;
            float hn = og * fast_tanh(cn);

            if (t == NT - 1) {
                out[bb * NH + (j0 + jj)] = hn;             // hidden [B,H]
                out[NB * NH + bb * NH + (j0 + jj)] = cn;   // cell   [B,H]
            } else {
                __stcg(&g_h[parity ^ 1][(j0 + jj) * NB + bb], hn);
            }
        }

        // Grid-wide barrier: release-increment, acquire-poll
        if (t < NT - 1) {
            __syncthreads();
            if (tid == 0) {
                bar_release_add(&g_bar);
                unsigned target = (unsigned)NCTA_B * (unsigned)(t + 1);
                while (bar_acquire_ld(&g_bar) < target) { }
            }
            __syncthreads();
        }
    }
}

// ---------------------------------------------------------------------------
extern "C" void kernel_launch(void* const* d_in, const int* in_sizes, int n_in,
                              void* d_out, int out_size) {
    const int*   tokens = (const int*)d_in[0];
    const float* emb    = (const float*)d_in[1];
    const float* W      = (const float*)d_in[2];
    const float* U      = (const float*)d_in[3];
    const float* bias   = (const float*)d_in[4];
    float* out = (float*)d_out;

    dim3 ga(NH / 16, (NB * NT) / 64);   // (32, 256)
    xz_kernel<<<ga, 256>>>(tokens, emb, W, bias);

    int smem = (int)(NH * US_STRIDE * sizeof(u64) +
                     (NH * HS_STRIDE + 16 * RED_ROW + 512 + 128) * sizeof(float));
    cudaFuncSetAttribute(lstm_kernel, cudaFuncAttributeMaxDynamicSharedMemorySize, smem);
    lstm_kernel<<<NCTA_B, THR_B, smem>>>(U, out);
}